// round 12
// baseline (speedup 1.0000x reference)
#include <cuda_runtime.h>

#define BATCH 4
#define NV 4096
#define NM 8192
#define BIGF 1e10f

#define NSTRIP 8               // m-strips per batch
#define STRIPM (NM / NSTRIP)   // 1024
#define BM     128             // p-cols per tile
#define NTILE  (STRIPM / BM)   // 8
#define NVB    (NV / 128)      // 32 v-row blocks
#define BLKS_PER_B (NSTRIP * NVB)   // 256

typedef unsigned long long u64;

// ------------------------ scratch (device globals, no allocs) ---------------
// g_dmin: [0, BATCH*NV) = d1 (per v row), [BATCH*NV, +BATCH*NM) = d2 (per p col)
// encoded floats; initialized to 0xFFFFFFFF by a memset node each launch.
__device__ unsigned g_dmin[BATCH * (NV + NM)];
__device__ float    g_res[BATCH];
__device__ unsigned g_done_b[BATCH];   // static zero-init; reset by last block
__device__ unsigned g_done_all;

// order-preserving float<->uint encoding so unsigned atomicMin == float min
__device__ __forceinline__ unsigned encf(float f) {
    unsigned u = __float_as_uint(f);
    return (u & 0x80000000u) ? ~u : (u | 0x80000000u);
}
__device__ __forceinline__ float decf(unsigned u) {
    return (u & 0x80000000u) ? __uint_as_float(u & 0x7FFFFFFFu)
                             : __uint_as_float(~u);
}

// ------------------------ packed f32x2 helpers ------------------------------
__device__ __forceinline__ u64 pack2(float lo, float hi) {
    u64 d;
    asm("mov.b64 %0, {%1, %2};" : "=l"(d) : "f"(lo), "f"(hi));
    return d;
}
__device__ __forceinline__ u64 fma2(u64 a, u64 b, u64 c) {
    u64 d;
    asm("fma.rn.f32x2 %0, %1, %2, %3;" : "=l"(d) : "l"(a), "l"(b), "l"(c));
    return d;
}
__device__ __forceinline__ u64 add2(u64 a, u64 b) {
    u64 d;
    asm("add.rn.f32x2 %0, %1, %2;" : "=l"(d) : "l"(a), "l"(b));
    return d;
}
__device__ __forceinline__ float2 asf2(u64 v) {
    union { u64 u; float2 f; } c; c.u = v; return c.f;
}

// ------------------------ fused chamfer + reduction --------------------------
// Block: 128 v-rows x 1024 p-cols (8 tiles of 128), 256 threads, grid=1024.
// occ 4 (registers trimmed): cmin is a scalar, p tile interleaved for LDS.128.
__global__ __launch_bounds__(256, 4) void chamfer_kernel(
        const float* __restrict__ vert, const float* __restrict__ pc,
        float* __restrict__ out) {
    __shared__ __align__(16) u64 sp[2][BM * 4];   // [c][4]: pxx,pyy,pzz,cpp
    __shared__ float sred[128 * 17];              // padded reduction scratch
    __shared__ __align__(16) float svx[128], svy[128], svz[128], scv[128];
    __shared__ bool  s_last;

    int b   = blockIdx.z;
    int y   = blockIdx.y;
    int n0  = y * 128;
    int s   = blockIdx.x;
    int mb0 = s * STRIPM;
    int tid = threadIdx.x;
    int ty  = tid >> 4;
    int tx  = tid & 15;

    // ---- transform my v rows (top surface gather) + p tile 0 ----
    if (tid < 128) {
        int r = n0 + tid;
        int i = r >> 6, k = r & 63;
        // vertices[b, c, i, 31, k]; shape (4,3,64,32,64)
        int base = ((b * 3) * 64 + i) * 2048 + 31 * 64 + k;
        float v0 = (vert[base]          - 0.5f) * 2.f;
        float v1 = (vert[base + 131072] - 0.5f) * 2.f;
        float v2 = (vert[base + 262144] - 0.5f) * 2.f;
        svx[tid] = v0; svy[tid] = v1; svz[tid] = v2;
        scv[tid] = fmaf(v0, v0, fmaf(v1, v1, v2 * v2));
    } else {
        int u = tid - 128;
        int m = mb0 + u;
        float p0 = pc[(b * 3 + 0) * NM + m];
        float p1 = pc[(b * 3 + 1) * NM + m];
        float p2 = pc[(b * 3 + 2) * NM + m];
        bool valid = (p0 != 0.f) || (p1 != 0.f) || (p2 != 0.f);
        float cp = valid ? fmaf(p0, p0, fmaf(p1, p1, p2 * p2)) : BIGF;
        sp[0][u * 4 + 0] = pack2(-2.f * p0, -2.f * p0);
        sp[0][u * 4 + 1] = pack2(-2.f * p1, -2.f * p1);
        sp[0][u * 4 + 2] = pack2(-2.f * p2, -2.f * p2);
        sp[0][u * 4 + 3] = pack2(cp, cp);
    }
    __syncthreads();

    // ---- my 8 v-rows as packed pairs (LDS.64 from SoA smem) ----
    u64 vx2[4], vy2[4], vz2[4], cv2[4];
#pragma unroll
    for (int q = 0; q < 4; q++) {
        int r = 8 * ty + 2 * q;
        vx2[q] = *(const u64*)&svx[r];
        vy2[q] = *(const u64*)&svy[r];
        vz2[q] = *(const u64*)&svz[r];
        cv2[q] = *(const u64*)&scv[r];
    }

    float rmin[8];
#pragma unroll
    for (int k = 0; k < 8; k++) rmin[k] = 3.4e38f;

    for (int t = 0; t < NTILE; t++) {
        int cur = t & 1, nxt = cur ^ 1;

        // prefetch + transform next tile (threads 128..255)
        float pnx, pny, pnz, pnw;
        int u = tid - 128;
        if (tid >= 128 && t + 1 < NTILE) {
            int m = mb0 + (t + 1) * BM + u;
            float p0 = pc[(b * 3 + 0) * NM + m];
            float p1 = pc[(b * 3 + 1) * NM + m];
            float p2 = pc[(b * 3 + 2) * NM + m];
            bool valid = (p0 != 0.f) || (p1 != 0.f) || (p2 != 0.f);
            pnw = valid ? fmaf(p0, p0, fmaf(p1, p1, p2 * p2)) : BIGF;
            pnx = -2.f * p0; pny = -2.f * p1; pnz = -2.f * p2;
        }

#pragma unroll
        for (int j = 0; j < 8; j++) {
            int c = tx + 16 * j;
            const u64* col = &sp[cur][c * 4];
            ulonglong2 h0 = *(const ulonglong2*)(col);      // pxx, pyy
            ulonglong2 h1 = *(const ulonglong2*)(col + 2);  // pzz, cpp
            float cj = 3.4e38f;
#pragma unroll
            for (int q = 0; q < 4; q++) {
                // tq = cp - 2 v.p  (both rows of the pair)
                u64 tq = fma2(vz2[q], h1.x, h1.y);
                tq = fma2(vy2[q], h0.y, tq);
                tq = fma2(vx2[q], h0.x, tq);
                float2 a = asf2(tq);
                rmin[2 * q]     = fminf(rmin[2 * q],     a.x);   // cv added at end
                rmin[2 * q + 1] = fminf(rmin[2 * q + 1], a.y);
                float2 e = asf2(add2(tq, cv2[q]));               // full d for p-side
                cj = fminf(cj, fminf(e.x, e.y));
            }
            sred[c * 17 + ty] = cj;    // dist2 partial for column c
        }

        // commit prefetched tile (everyone is past tile t-1's reads)
        if (tid >= 128 && t + 1 < NTILE) {
            sp[nxt][u * 4 + 0] = pack2(pnx, pnx);
            sp[nxt][u * 4 + 1] = pack2(pny, pny);
            sp[nxt][u * 4 + 2] = pack2(pnz, pnz);
            sp[nxt][u * 4 + 3] = pack2(pnw, pnw);
        }
        __syncthreads();

        if (tid < 128) {
            float mn = sred[tid * 17];
#pragma unroll
            for (int k = 1; k < 16; k++) mn = fminf(mn, sred[tid * 17 + k]);
            atomicMin(&g_dmin[BATCH * NV + b * NM + mb0 + t * BM + tid], encf(mn));
        }
        __syncthreads();
    }

    // ---- dist1 partial: once per block ----
#pragma unroll
    for (int k = 0; k < 8; k++)
        sred[(8 * ty + k) * 17 + tx] = rmin[k];
    __syncthreads();
    if (tid < 128) {
        float mn = sred[tid * 17];
#pragma unroll
        for (int k = 1; k < 16; k++) mn = fminf(mn, sred[tid * 17 + k]);
        atomicMin(&g_dmin[b * NV + n0 + tid], encf(mn + scv[tid]));
    }

    // ================== fused epilogue ==================
    __threadfence();
    if (tid == 0) {
        unsigned c = atomicAdd(&g_done_b[b], 1u);
        s_last = (c == BLKS_PER_B - 1);
    }
    __syncthreads();
    if (!s_last) return;

    // last block of batch b: reduce this batch's mins (48 KB)
    float s1 = 0.f, s2 = 0.f, c2 = 0.f;
#pragma unroll
    for (int i = tid; i < NV / 4; i += 256) {
        uint4 d = *(const uint4*)&g_dmin[b * NV + i * 4];
        s1 += decf(d.x) + decf(d.y) + decf(d.z) + decf(d.w);
    }
#pragma unroll
    for (int i = tid; i < NM / 4; i += 256) {
        uint4 d = *(const uint4*)&g_dmin[BATCH * NV + b * NM + i * 4];
        float v;
        v = decf(d.x); if (v < 1e9f) { s2 += v; c2 += 1.f; }
        v = decf(d.y); if (v < 1e9f) { s2 += v; c2 += 1.f; }
        v = decf(d.z); if (v < 1e9f) { s2 += v; c2 += 1.f; }
        v = decf(d.w); if (v < 1e9f) { s2 += v; c2 += 1.f; }
    }

    // block reduction (warp shuffles + smem via sred)
    int lane = tid & 31, wd = tid >> 5;
#pragma unroll
    for (int o = 16; o > 0; o >>= 1) {
        s1 += __shfl_down_sync(0xffffffffu, s1, o);
        s2 += __shfl_down_sync(0xffffffffu, s2, o);
        c2 += __shfl_down_sync(0xffffffffu, c2, o);
    }
    if (lane == 0) { sred[wd] = s1; sred[8 + wd] = s2; sred[16 + wd] = c2; }
    __syncthreads();

    if (tid == 0) {
        float t1 = 0.f, t2 = 0.f, tc = 0.f;
#pragma unroll
        for (int w = 0; w < 8; w++) { t1 += sred[w]; t2 += sred[8 + w]; tc += sred[16 + w]; }
        g_res[b] = t1 / (float)NV + t2 / fmaxf(tc, 1.f);
        __threadfence();
        unsigned c = atomicAdd(&g_done_all, 1u);
        if (c == BATCH - 1) {
            float acc = 0.f;
#pragma unroll
            for (int bb = 0; bb < BATCH; bb++) acc += g_res[bb];
            out[0] = acc / (float)BATCH;
            // reset counters for the next graph replay
            g_done_all = 0u;
#pragma unroll
            for (int bb = 0; bb < BATCH; bb++) g_done_b[bb] = 0u;
        }
    }
}

// ------------------------ launch --------------------------------------------
extern "C" void kernel_launch(void* const* d_in, const int* in_sizes, int n_in,
                              void* d_out, int out_size) {
    const float* vert = (const float*)d_in[0];
    const float* pc   = (const float*)d_in[1];
    if (in_sizes[0] == BATCH * 3 * NM) {   // defensive input identification
        vert = (const float*)d_in[1];
        pc   = (const float*)d_in[0];
    }

    // init min arrays to 0xFFFFFFFF (> any encoded float) — capturable memset
    void* dmin_ptr = nullptr;
    cudaGetSymbolAddress(&dmin_ptr, g_dmin);
    cudaMemsetAsync(dmin_ptr, 0xFF, BATCH * (NV + NM) * sizeof(unsigned), 0);

    dim3 grid(NSTRIP, NVB, BATCH);
    chamfer_kernel<<<grid, 256>>>(vert, pc, (float*)d_out);
}

// round 13
// speedup vs baseline: 1.2489x; 1.2489x over previous
#include <cuda_runtime.h>

#define BATCH 4
#define NV 4096
#define NM 8192
#define BIGF 1e10f

#define NSTRIP 8               // m-strips per batch
#define STRIPM (NM / NSTRIP)   // 1024
#define BM     128             // p-cols per tile
#define NTILE  (STRIPM / BM)   // 8
#define NVB    (NV / 128)      // 32 v-row blocks

typedef unsigned long long u64;

// ------------------------ scratch (device globals, no allocs) ---------------
__device__ float g_d1p[NSTRIP][BATCH * NV];   // min over a strip's p, per v row
__device__ float g_d2p[NVB][BATCH * NM];      // min over a 128-row v block, per p col
__device__ float g_sum1[BATCH], g_sum2[BATCH], g_cnt[BATCH];  // reset by final writer
__device__ unsigned g_done1[BATCH * NVB];     // d1 groups (b,y): 8 arrivals
__device__ unsigned g_done2[BATCH * NSTRIP];  // d2 groups (b,s): 32 arrivals
__device__ unsigned g_done_all;               // 160 group completions

// ------------------------ packed f32x2 helpers ------------------------------
__device__ __forceinline__ u64 pack2(float lo, float hi) {
    u64 d;
    asm("mov.b64 %0, {%1, %2};" : "=l"(d) : "f"(lo), "f"(hi));
    return d;
}
__device__ __forceinline__ u64 fma2(u64 a, u64 b, u64 c) {
    u64 d;
    asm("fma.rn.f32x2 %0, %1, %2, %3;" : "=l"(d) : "l"(a), "l"(b), "l"(c));
    return d;
}
__device__ __forceinline__ u64 add2(u64 a, u64 b) {
    u64 d;
    asm("add.rn.f32x2 %0, %1, %2;" : "=l"(d) : "l"(a), "l"(b));
    return d;
}
__device__ __forceinline__ float2 asf2(u64 v) {
    union { u64 u; float2 f; } c; c.u = v; return c.f;
}

// block-wide sum of one value (uses 8-entry smem scratch)
__device__ __forceinline__ float block_sum(float v, float* sc, int tid) {
    int lane = tid & 31, wd = tid >> 5;
#pragma unroll
    for (int o = 16; o > 0; o >>= 1) v += __shfl_down_sync(0xffffffffu, v, o);
    if (lane == 0) sc[wd] = v;
    __syncthreads();
    float r = 0.f;
    if (tid == 0) {
#pragma unroll
        for (int w = 0; w < 8; w++) r += sc[w];
    }
    __syncthreads();
    return r;   // valid on tid 0
}

// ------------------------ fused chamfer + distributed reduction -------------
// Block: 128 v-rows x 1024 p-cols (8 tiles of 128), 256 threads, grid=1024.
// R9 main loop (SoA broadcast LDS.64, occ 3, plain-store partials) + group
// epilogues: last block per (b,y) reduces d1, last per (b,s) reduces d2,
// last group overall writes out. All counters self-reset for graph replay.
__global__ __launch_bounds__(256, 3) void chamfer_kernel(
        const float* __restrict__ vert, const float* __restrict__ pc,
        float* __restrict__ out) {
    __shared__ u64   spx[2][BM];
    __shared__ u64   spy[2][BM];
    __shared__ u64   spz[2][BM];
    __shared__ u64   spw[2][BM];
    __shared__ float sred[128 * 17];   // padded reduction scratch
    __shared__ __align__(16) float svx[128], svy[128], svz[128], scv[128];
    __shared__ bool  s_last1, s_last2;

    int b   = blockIdx.z;
    int y   = blockIdx.y;
    int n0  = y * 128;
    int s   = blockIdx.x;
    int mb0 = s * STRIPM;
    int tid = threadIdx.x;
    int ty  = tid >> 4;
    int tx  = tid & 15;

    // ---- transform my v rows (top surface gather) + p tile 0 ----
    if (tid < 128) {
        int r = n0 + tid;
        int i = r >> 6, k = r & 63;
        // vertices[b, c, i, 31, k]; shape (4,3,64,32,64)
        int base = ((b * 3) * 64 + i) * 2048 + 31 * 64 + k;
        float v0 = (vert[base]          - 0.5f) * 2.f;
        float v1 = (vert[base + 131072] - 0.5f) * 2.f;
        float v2 = (vert[base + 262144] - 0.5f) * 2.f;
        svx[tid] = v0; svy[tid] = v1; svz[tid] = v2;
        scv[tid] = fmaf(v0, v0, fmaf(v1, v1, v2 * v2));
    } else {
        int u = tid - 128;
        int m = mb0 + u;
        float p0 = pc[(b * 3 + 0) * NM + m];
        float p1 = pc[(b * 3 + 1) * NM + m];
        float p2 = pc[(b * 3 + 2) * NM + m];
        bool valid = (p0 != 0.f) || (p1 != 0.f) || (p2 != 0.f);
        float cp = valid ? fmaf(p0, p0, fmaf(p1, p1, p2 * p2)) : BIGF;
        spx[0][u] = pack2(-2.f * p0, -2.f * p0);
        spy[0][u] = pack2(-2.f * p1, -2.f * p1);
        spz[0][u] = pack2(-2.f * p2, -2.f * p2);
        spw[0][u] = pack2(cp, cp);
    }
    __syncthreads();

    // ---- my 8 v-rows as packed pairs (broadcast LDS.64 from SoA smem) ----
    u64 vx2[4], vy2[4], vz2[4], cv2[4];
#pragma unroll
    for (int q = 0; q < 4; q++) {
        int r = 8 * ty + 2 * q;
        vx2[q] = *(const u64*)&svx[r];
        vy2[q] = *(const u64*)&svy[r];
        vz2[q] = *(const u64*)&svz[r];
        cv2[q] = *(const u64*)&scv[r];
    }

    float rmin[8];
#pragma unroll
    for (int k = 0; k < 8; k++) rmin[k] = 3.4e38f;

    for (int t = 0; t < NTILE; t++) {
        int cur = t & 1, nxt = cur ^ 1;

        // prefetch + transform next tile (threads 128..255)
        float pnx, pny, pnz, pnw;
        int u = tid - 128;
        if (tid >= 128 && t + 1 < NTILE) {
            int m = mb0 + (t + 1) * BM + u;
            float p0 = pc[(b * 3 + 0) * NM + m];
            float p1 = pc[(b * 3 + 1) * NM + m];
            float p2 = pc[(b * 3 + 2) * NM + m];
            bool valid = (p0 != 0.f) || (p1 != 0.f) || (p2 != 0.f);
            pnw = valid ? fmaf(p0, p0, fmaf(p1, p1, p2 * p2)) : BIGF;
            pnx = -2.f * p0; pny = -2.f * p1; pnz = -2.f * p2;
        }

        float cmin[8];
#pragma unroll
        for (int j = 0; j < 8; j++) cmin[j] = 3.4e38f;

#pragma unroll
        for (int j = 0; j < 8; j++) {
            int c = tx + 16 * j;
            u64 pxx = spx[cur][c];
            u64 pyy = spy[cur][c];
            u64 pzz = spz[cur][c];
            u64 cpp = spw[cur][c];
#pragma unroll
            for (int q = 0; q < 4; q++) {
                // tq = cp - 2 v.p  (both rows of the pair)
                u64 tq = fma2(vz2[q], pzz, cpp);
                tq = fma2(vy2[q], pyy, tq);
                tq = fma2(vx2[q], pxx, tq);
                float2 a = asf2(tq);
                rmin[2 * q]     = fminf(rmin[2 * q],     a.x);   // cv added at end
                rmin[2 * q + 1] = fminf(rmin[2 * q + 1], a.y);
                float2 e = asf2(add2(tq, cv2[q]));               // full d for p-side
                cmin[j] = fminf(cmin[j], fminf(e.x, e.y));
            }
        }

        // commit prefetched tile (everyone is past tile t-1's reads)
        if (tid >= 128 && t + 1 < NTILE) {
            spx[nxt][u] = pack2(pnx, pnx);
            spy[nxt][u] = pack2(pny, pny);
            spz[nxt][u] = pack2(pnz, pnz);
            spw[nxt][u] = pack2(pnw, pnw);
        }

        // ---- dist2 partials: col tx+16j, across ty ----
#pragma unroll
        for (int j = 0; j < 8; j++)
            sred[(tx + 16 * j) * 17 + ty] = cmin[j];
        __syncthreads();

        if (tid < 128) {
            float mn = sred[tid * 17];
#pragma unroll
            for (int k = 1; k < 16; k++) mn = fminf(mn, sred[tid * 17 + k]);
            g_d2p[y][b * NM + mb0 + t * BM + tid] = mn;   // coalesced store
        }
        __syncthreads();
    }

    // ---- dist1 partial: once per block ----
#pragma unroll
    for (int k = 0; k < 8; k++)
        sred[(8 * ty + k) * 17 + tx] = rmin[k];
    __syncthreads();
    if (tid < 128) {
        float mn = sred[tid * 17];
#pragma unroll
        for (int k = 1; k < 16; k++) mn = fminf(mn, sred[tid * 17 + k]);
        g_d1p[s][b * NV + n0 + tid] = mn + scv[tid];      // coalesced store
    }

    // ================== distributed epilogue ==================
    __threadfence();
    if (tid == 0) {
        unsigned c1 = atomicAdd(&g_done1[b * NVB + y], 1u);
        s_last1 = (c1 == NSTRIP - 1);
        if (s_last1) g_done1[b * NVB + y] = 0u;           // self-reset
        unsigned c2 = atomicAdd(&g_done2[b * NSTRIP + s], 1u);
        s_last2 = (c2 == NVB - 1);
        if (s_last2) g_done2[b * NSTRIP + s] = 0u;        // self-reset
    }
    __syncthreads();

    int ngroups_done = 0;

    if (s_last1) {
        // reduce d1 for rows [n0, n0+128): min over 8 strips, then sum
        float v = 0.f;
        if (tid < 128) {
            float mn = g_d1p[0][b * NV + n0 + tid];
#pragma unroll
            for (int ss = 1; ss < NSTRIP; ss++)
                mn = fminf(mn, g_d1p[ss][b * NV + n0 + tid]);
            v = mn;
        }
        float tot = block_sum(v, sred, tid);
        if (tid == 0) atomicAdd(&g_sum1[b], tot);
        ngroups_done++;
    }

    if (s_last2) {
        // reduce d2 for m in [mb0, mb0+1024): min over 32 y-blocks, mask, sum
        int m = mb0 + tid * 4;
        float4 mn = make_float4(3.4e38f, 3.4e38f, 3.4e38f, 3.4e38f);
#pragma unroll
        for (int yy = 0; yy < NVB; yy++) {
            float4 w = *(const float4*)&g_d2p[yy][b * NM + m];
            mn.x = fminf(mn.x, w.x); mn.y = fminf(mn.y, w.y);
            mn.z = fminf(mn.z, w.z); mn.w = fminf(mn.w, w.w);
        }
        float sv = 0.f, cv = 0.f;   // invalid cols carry cp=BIGF -> min >= 1e10
        if (mn.x < 1e9f) { sv += mn.x; cv += 1.f; }
        if (mn.y < 1e9f) { sv += mn.y; cv += 1.f; }
        if (mn.z < 1e9f) { sv += mn.z; cv += 1.f; }
        if (mn.w < 1e9f) { sv += mn.w; cv += 1.f; }
        float tot = block_sum(sv, sred, tid);
        float cnt = block_sum(cv, sred, tid);
        if (tid == 0) {
            atomicAdd(&g_sum2[b], tot);
            atomicAdd(&g_cnt[b],  cnt);
        }
        ngroups_done++;
    }

    if (tid == 0 && ngroups_done) {
        __threadfence();
        unsigned c = atomicAdd(&g_done_all, (unsigned)ngroups_done);
        if (c + (unsigned)ngroups_done == BATCH * (NVB + NSTRIP)) {  // 160
            float acc = 0.f;
#pragma unroll
            for (int bb = 0; bb < BATCH; bb++)
                acc += g_sum1[bb] / (float)NV + g_sum2[bb] / fmaxf(g_cnt[bb], 1.f);
            out[0] = acc / (float)BATCH;
            // reset for next graph replay
            g_done_all = 0u;
#pragma unroll
            for (int bb = 0; bb < BATCH; bb++) {
                g_sum1[bb] = 0.f; g_sum2[bb] = 0.f; g_cnt[bb] = 0.f;
            }
        }
    }
}

// ------------------------ launch --------------------------------------------
extern "C" void kernel_launch(void* const* d_in, const int* in_sizes, int n_in,
                              void* d_out, int out_size) {
    const float* vert = (const float*)d_in[0];
    const float* pc   = (const float*)d_in[1];
    if (in_sizes[0] == BATCH * 3 * NM) {   // defensive input identification
        vert = (const float*)d_in[1];
        pc   = (const float*)d_in[0];
    }

    dim3 grid(NSTRIP, NVB, BATCH);
    chamfer_kernel<<<grid, 256>>>(vert, pc, (float*)d_out);
}

// round 14
// speedup vs baseline: 1.3965x; 1.1182x over previous
#include <cuda_runtime.h>

#define BATCH 4
#define NV 4096
#define NM 8192
#define BIGF 1e10f

#define NSTRIP 8               // m-strips per batch
#define STRIPM (NM / NSTRIP)   // 1024
#define BM     256             // p-cols per tile
#define NTILE  (STRIPM / BM)   // 4
#define NVB    (NV / 128)      // 32 v-row blocks

typedef unsigned long long u64;

// ------------------------ scratch (device globals, no allocs) ---------------
__device__ float g_d1p[NSTRIP][BATCH * NV];   // min over a strip's p, per v row
__device__ float g_d2p[NVB][BATCH * NM];      // min over a 128-row v block, per p col
__device__ float g_sum1[BATCH], g_sum2[BATCH], g_cnt[BATCH];
__device__ unsigned g_done;

// ------------------------ packed f32x2 helpers ------------------------------
__device__ __forceinline__ u64 pack2(float lo, float hi) {
    u64 d;
    asm("mov.b64 %0, {%1, %2};" : "=l"(d) : "f"(lo), "f"(hi));
    return d;
}
__device__ __forceinline__ u64 fma2(u64 a, u64 b, u64 c) {
    u64 d;
    asm("fma.rn.f32x2 %0, %1, %2, %3;" : "=l"(d) : "l"(a), "l"(b), "l"(c));
    return d;
}
__device__ __forceinline__ u64 add2(u64 a, u64 b) {
    u64 d;
    asm("add.rn.f32x2 %0, %1, %2;" : "=l"(d) : "l"(a), "l"(b));
    return d;
}
__device__ __forceinline__ float2 asf2(u64 v) {
    union { u64 u; float2 f; } c; c.u = v; return c.f;
}

// ------------------------ 1) fused transform + pairwise min ------------------
// Block: 128 v-rows x 1024 p-cols (4 tiles of 256), 256 threads, grid=1024.
// SoA broadcast-LDS.64 p layout (proven), cmin scalar -> sred inside j loop,
// 2 syncs per tile (8 total).
__global__ __launch_bounds__(256, 3) void chamfer_kernel(
        const float* __restrict__ vert, const float* __restrict__ pc) {
    __shared__ u64   spx[2][BM];
    __shared__ u64   spy[2][BM];
    __shared__ u64   spz[2][BM];
    __shared__ u64   spw[2][BM];
    __shared__ float sred[BM * 17];    // padded reduction scratch
    __shared__ __align__(16) float svx[128], svy[128], svz[128], scv[128];

    int b   = blockIdx.z;
    int y   = blockIdx.y;
    int n0  = y * 128;
    int s   = blockIdx.x;
    int mb0 = s * STRIPM;
    int tid = threadIdx.x;
    int ty  = tid >> 4;
    int tx  = tid & 15;

    // one block zeroes the final-stage accumulators (nobody reads them in K1)
    if (blockIdx.x == 0 && blockIdx.y == 0 && blockIdx.z == 0 && tid < BATCH) {
        g_sum1[tid] = 0.f; g_sum2[tid] = 0.f; g_cnt[tid] = 0.f;
        if (tid == 0) g_done = 0u;
    }

    // ---- transform my v rows (top surface gather) ----
    if (tid < 128) {
        int r = n0 + tid;
        int i = r >> 6, k = r & 63;
        // vertices[b, c, i, 31, k]; shape (4,3,64,32,64)
        int base = ((b * 3) * 64 + i) * 2048 + 31 * 64 + k;
        float v0 = (vert[base]          - 0.5f) * 2.f;
        float v1 = (vert[base + 131072] - 0.5f) * 2.f;
        float v2 = (vert[base + 262144] - 0.5f) * 2.f;
        svx[tid] = v0; svy[tid] = v1; svz[tid] = v2;
        scv[tid] = fmaf(v0, v0, fmaf(v1, v1, v2 * v2));
    }
    // ---- p tile 0: all 256 threads, 1 column each ----
    {
        int m = mb0 + tid;
        float p0 = pc[(b * 3 + 0) * NM + m];
        float p1 = pc[(b * 3 + 1) * NM + m];
        float p2 = pc[(b * 3 + 2) * NM + m];
        bool valid = (p0 != 0.f) || (p1 != 0.f) || (p2 != 0.f);
        float cp = valid ? fmaf(p0, p0, fmaf(p1, p1, p2 * p2)) : BIGF;
        spx[0][tid] = pack2(-2.f * p0, -2.f * p0);
        spy[0][tid] = pack2(-2.f * p1, -2.f * p1);
        spz[0][tid] = pack2(-2.f * p2, -2.f * p2);
        spw[0][tid] = pack2(cp, cp);
    }
    __syncthreads();

    // ---- my 8 v-rows as packed pairs (broadcast LDS.64 from SoA smem) ----
    u64 vx2[4], vy2[4], vz2[4], cv2[4];
#pragma unroll
    for (int q = 0; q < 4; q++) {
        int r = 8 * ty + 2 * q;
        vx2[q] = *(const u64*)&svx[r];
        vy2[q] = *(const u64*)&svy[r];
        vz2[q] = *(const u64*)&svz[r];
        cv2[q] = *(const u64*)&scv[r];
    }

    float rmin[8];
#pragma unroll
    for (int k = 0; k < 8; k++) rmin[k] = 3.4e38f;

    for (int t = 0; t < NTILE; t++) {
        int cur = t & 1, nxt = cur ^ 1;

        // prefetch + transform next tile (all 256 threads, 1 column each)
        float pnx, pny, pnz, pnw;
        if (t + 1 < NTILE) {
            int m = mb0 + (t + 1) * BM + tid;
            float p0 = pc[(b * 3 + 0) * NM + m];
            float p1 = pc[(b * 3 + 1) * NM + m];
            float p2 = pc[(b * 3 + 2) * NM + m];
            bool valid = (p0 != 0.f) || (p1 != 0.f) || (p2 != 0.f);
            pnw = valid ? fmaf(p0, p0, fmaf(p1, p1, p2 * p2)) : BIGF;
            pnx = -2.f * p0; pny = -2.f * p1; pnz = -2.f * p2;
        }

#pragma unroll
        for (int j = 0; j < 16; j++) {
            int c = tx + 16 * j;
            u64 pxx = spx[cur][c];
            u64 pyy = spy[cur][c];
            u64 pzz = spz[cur][c];
            u64 cpp = spw[cur][c];
            float cj = 3.4e38f;
#pragma unroll
            for (int q = 0; q < 4; q++) {
                // tq = cp - 2 v.p  (both rows of the pair)
                u64 tq = fma2(vz2[q], pzz, cpp);
                tq = fma2(vy2[q], pyy, tq);
                tq = fma2(vx2[q], pxx, tq);
                float2 a = asf2(tq);
                rmin[2 * q]     = fminf(rmin[2 * q],     a.x);   // cv added at end
                rmin[2 * q + 1] = fminf(rmin[2 * q + 1], a.y);
                float2 e = asf2(add2(tq, cv2[q]));               // full d for p-side
                cj = fminf(cj, fminf(e.x, e.y));
            }
            sred[c * 17 + ty] = cj;   // conflict-free: gcd(17,32)=1
        }
        __syncthreads();

        // commit prefetched tile (buffer nxt was last read in tile t-1)
        if (t + 1 < NTILE) {
            spx[nxt][tid] = pack2(pnx, pnx);
            spy[nxt][tid] = pack2(pny, pny);
            spz[nxt][tid] = pack2(pnz, pnz);
            spw[nxt][tid] = pack2(pnw, pnw);
        }

        // ---- dist2: every thread reduces one of the 256 columns ----
        {
            float mn = sred[tid * 17];
#pragma unroll
            for (int k = 1; k < 16; k++) mn = fminf(mn, sred[tid * 17 + k]);
            g_d2p[y][b * NM + mb0 + t * BM + tid] = mn;   // coalesced store
        }
        __syncthreads();
    }

    // ---- dist1 partial: once per block ----
#pragma unroll
    for (int k = 0; k < 8; k++)
        sred[(8 * ty + k) * 17 + tx] = rmin[k];
    __syncthreads();
    if (tid < 128) {
        float mn = sred[tid * 17];
#pragma unroll
        for (int k = 1; k < 16; k++) mn = fminf(mn, sred[tid * 17 + k]);
        g_d1p[s][b * NV + n0 + tid] = mn + scv[tid];      // coalesced store
    }
}

// ------------------------ 2) final reduction --------------------------------
// 256 blocks (64 per batch), 256 threads; parallel across the reduction dim.
// Mask via sentinel: invalid p-cols carry mins >= 1e10 (cp=BIGF), no pc reads.
__global__ void final_kernel(float* __restrict__ out) {
    __shared__ float4 p2[256];    // d2 stage-1 partials
    __shared__ float2 p1[256];    // d1 stage-1 partials
    __shared__ float sh[4];
    __shared__ bool last;
    int tid  = threadIdx.x;
    int b    = blockIdx.x >> 6;
    int part = blockIdx.x & 63;

    // ---- d2 stage 1: block covers 128 m-cols = 32 quads; 8 yy-groups of 4 ----
    {
        int q  = tid & 31;          // m-quad
        int yg = tid >> 5;          // yy-group (0..7)
        int m  = part * 128 + q * 4;
        float4 mn = make_float4(3.4e38f, 3.4e38f, 3.4e38f, 3.4e38f);
#pragma unroll
        for (int k = 0; k < 4; k++) {
            float4 v = *(const float4*)&g_d2p[yg * 4 + k][b * NM + m];
            mn.x = fminf(mn.x, v.x); mn.y = fminf(mn.y, v.y);
            mn.z = fminf(mn.z, v.z); mn.w = fminf(mn.w, v.w);
        }
        p2[tid] = mn;
    }
    // ---- d1 stage 1: block covers 64 v-rows = 32 pairs; 8 strips ----
    {
        int pr = tid & 31;          // n-pair
        int sg = tid >> 5;          // strip (0..7)
        int n  = part * 64 + pr * 2;
        p1[tid] = *(const float2*)&g_d1p[sg][b * NV + n];
    }
    __syncthreads();

    // ---- stage 2 + sentinel-masked accumulate ----
    float s1 = 0.f, s2 = 0.f, c2 = 0.f;
    if (tid < 32) {
        float4 mn = p2[tid];
#pragma unroll
        for (int k = 1; k < 8; k++) {
            float4 v = p2[tid + 32 * k];
            mn.x = fminf(mn.x, v.x); mn.y = fminf(mn.y, v.y);
            mn.z = fminf(mn.z, v.z); mn.w = fminf(mn.w, v.w);
        }
        if (mn.x < 1e9f) { s2 += mn.x; c2 += 1.f; }
        if (mn.y < 1e9f) { s2 += mn.y; c2 += 1.f; }
        if (mn.z < 1e9f) { s2 += mn.z; c2 += 1.f; }
        if (mn.w < 1e9f) { s2 += mn.w; c2 += 1.f; }
    } else if (tid < 64) {
        int pr = tid - 32;
        float2 mn = p1[pr];
#pragma unroll
        for (int k = 1; k < 8; k++) {
            float2 v = p1[pr + 32 * k];
            mn.x = fminf(mn.x, v.x); mn.y = fminf(mn.y, v.y);
        }
        s1 = mn.x + mn.y;
    }

#pragma unroll
    for (int o = 16; o > 0; o >>= 1) {
        s1 += __shfl_down_sync(0xffffffffu, s1, o);
        s2 += __shfl_down_sync(0xffffffffu, s2, o);
        c2 += __shfl_down_sync(0xffffffffu, c2, o);
    }
    if (tid == 0)  { sh[0] = s2; sh[1] = c2; }
    if (tid == 32) { sh[2] = s1; }
    __syncthreads();

    if (tid == 0) {
        atomicAdd(&g_sum1[b], sh[2]);
        atomicAdd(&g_sum2[b], sh[0]);
        atomicAdd(&g_cnt[b],  sh[1]);
        __threadfence();
        unsigned done = atomicAdd(&g_done, 1u);
        last = (done == gridDim.x - 1);
    }
    __syncthreads();

    if (last && tid == 0) {
        float acc = 0.f;
        for (int bb = 0; bb < BATCH; bb++)
            acc += g_sum1[bb] / (float)NV + g_sum2[bb] / fmaxf(g_cnt[bb], 1.f);
        out[0] = acc / (float)BATCH;
    }
}

// ------------------------ launch --------------------------------------------
extern "C" void kernel_launch(void* const* d_in, const int* in_sizes, int n_in,
                              void* d_out, int out_size) {
    const float* vert = (const float*)d_in[0];
    const float* pc   = (const float*)d_in[1];
    if (in_sizes[0] == BATCH * 3 * NM) {   // defensive input identification
        vert = (const float*)d_in[1];
        pc   = (const float*)d_in[0];
    }

    dim3 grid(NSTRIP, NVB, BATCH);
    chamfer_kernel<<<grid, 256>>>(vert, pc);
    final_kernel<<<256, 256>>>((float*)d_out);
}

// round 15
// speedup vs baseline: 1.3996x; 1.0022x over previous
#include <cuda_runtime.h>

#define BATCH 4
#define NV 4096
#define NM 8192
#define BIGF 1e10f

#define NSTRIP 16              // m-strips per batch
#define STRIPM (NM / NSTRIP)   // 512
#define BM     256             // p-cols per tile
#define NTILE  (STRIPM / BM)   // 2
#define NVB    (NV / 128)      // 32 v-row blocks

typedef unsigned long long u64;

// ------------------------ scratch (device globals, no allocs) ---------------
__device__ float g_d1p[NSTRIP][BATCH * NV];   // min over a strip's p, per v row
__device__ float g_d2p[NVB][BATCH * NM];      // min over a 128-row v block, per p col
__device__ float g_sum1[BATCH], g_sum2[BATCH], g_cnt[BATCH];
__device__ unsigned g_done;

// ------------------------ packed f32x2 helpers ------------------------------
__device__ __forceinline__ u64 pack2(float lo, float hi) {
    u64 d;
    asm("mov.b64 %0, {%1, %2};" : "=l"(d) : "f"(lo), "f"(hi));
    return d;
}
__device__ __forceinline__ u64 fma2(u64 a, u64 b, u64 c) {
    u64 d;
    asm("fma.rn.f32x2 %0, %1, %2, %3;" : "=l"(d) : "l"(a), "l"(b), "l"(c));
    return d;
}
__device__ __forceinline__ u64 add2(u64 a, u64 b) {
    u64 d;
    asm("add.rn.f32x2 %0, %1, %2;" : "=l"(d) : "l"(a), "l"(b));
    return d;
}
__device__ __forceinline__ float2 asf2(u64 v) {
    union { u64 u; float2 f; } c; c.u = v; return c.f;
}

// ------------------------ 1) fused transform + pairwise min ------------------
// Block: 128 v-rows x 512 p-cols (2 tiles of 256), 256 threads, grid=2048.
// Finer blocks shrink the last-wave tail (4.6 waves vs 2.3).
__global__ __launch_bounds__(256, 3) void chamfer_kernel(
        const float* __restrict__ vert, const float* __restrict__ pc) {
    __shared__ u64   spx[2][BM];
    __shared__ u64   spy[2][BM];
    __shared__ u64   spz[2][BM];
    __shared__ u64   spw[2][BM];
    __shared__ float sred[BM * 17];    // padded reduction scratch
    __shared__ __align__(16) float svx[128], svy[128], svz[128], scv[128];

    int b   = blockIdx.z;
    int y   = blockIdx.y;
    int n0  = y * 128;
    int s   = blockIdx.x;
    int mb0 = s * STRIPM;
    int tid = threadIdx.x;
    int ty  = tid >> 4;
    int tx  = tid & 15;

    // one block zeroes the final-stage accumulators (nobody reads them in K1)
    if (blockIdx.x == 0 && blockIdx.y == 0 && blockIdx.z == 0 && tid < BATCH) {
        g_sum1[tid] = 0.f; g_sum2[tid] = 0.f; g_cnt[tid] = 0.f;
        if (tid == 0) g_done = 0u;
    }

    // ---- transform my v rows (top surface gather) ----
    if (tid < 128) {
        int r = n0 + tid;
        int i = r >> 6, k = r & 63;
        // vertices[b, c, i, 31, k]; shape (4,3,64,32,64)
        int base = ((b * 3) * 64 + i) * 2048 + 31 * 64 + k;
        float v0 = (vert[base]          - 0.5f) * 2.f;
        float v1 = (vert[base + 131072] - 0.5f) * 2.f;
        float v2 = (vert[base + 262144] - 0.5f) * 2.f;
        svx[tid] = v0; svy[tid] = v1; svz[tid] = v2;
        scv[tid] = fmaf(v0, v0, fmaf(v1, v1, v2 * v2));
    }
    // ---- p tile 0: all 256 threads, 1 column each ----
    {
        int m = mb0 + tid;
        float p0 = pc[(b * 3 + 0) * NM + m];
        float p1 = pc[(b * 3 + 1) * NM + m];
        float p2 = pc[(b * 3 + 2) * NM + m];
        bool valid = (p0 != 0.f) || (p1 != 0.f) || (p2 != 0.f);
        float cp = valid ? fmaf(p0, p0, fmaf(p1, p1, p2 * p2)) : BIGF;
        spx[0][tid] = pack2(-2.f * p0, -2.f * p0);
        spy[0][tid] = pack2(-2.f * p1, -2.f * p1);
        spz[0][tid] = pack2(-2.f * p2, -2.f * p2);
        spw[0][tid] = pack2(cp, cp);
    }
    __syncthreads();

    // ---- my 8 v-rows as packed pairs (broadcast LDS.64 from SoA smem) ----
    u64 vx2[4], vy2[4], vz2[4], cv2[4];
#pragma unroll
    for (int q = 0; q < 4; q++) {
        int r = 8 * ty + 2 * q;
        vx2[q] = *(const u64*)&svx[r];
        vy2[q] = *(const u64*)&svy[r];
        vz2[q] = *(const u64*)&svz[r];
        cv2[q] = *(const u64*)&scv[r];
    }

    float rmin[8];
#pragma unroll
    for (int k = 0; k < 8; k++) rmin[k] = 3.4e38f;

#pragma unroll
    for (int t = 0; t < NTILE; t++) {
        int cur = t & 1, nxt = cur ^ 1;

        // prefetch + transform next tile (all 256 threads, 1 column each)
        float pnx, pny, pnz, pnw;
        if (t + 1 < NTILE) {
            int m = mb0 + (t + 1) * BM + tid;
            float p0 = pc[(b * 3 + 0) * NM + m];
            float p1 = pc[(b * 3 + 1) * NM + m];
            float p2 = pc[(b * 3 + 2) * NM + m];
            bool valid = (p0 != 0.f) || (p1 != 0.f) || (p2 != 0.f);
            pnw = valid ? fmaf(p0, p0, fmaf(p1, p1, p2 * p2)) : BIGF;
            pnx = -2.f * p0; pny = -2.f * p1; pnz = -2.f * p2;
        }

#pragma unroll
        for (int j = 0; j < 16; j++) {
            int c = tx + 16 * j;
            u64 pxx = spx[cur][c];
            u64 pyy = spy[cur][c];
            u64 pzz = spz[cur][c];
            u64 cpp = spw[cur][c];
            float cj = 3.4e38f;
#pragma unroll
            for (int q = 0; q < 4; q++) {
                // tq = cp - 2 v.p  (both rows of the pair)
                u64 tq = fma2(vz2[q], pzz, cpp);
                tq = fma2(vy2[q], pyy, tq);
                tq = fma2(vx2[q], pxx, tq);
                float2 a = asf2(tq);
                rmin[2 * q]     = fminf(rmin[2 * q],     a.x);   // cv added at end
                rmin[2 * q + 1] = fminf(rmin[2 * q + 1], a.y);
                float2 e = asf2(add2(tq, cv2[q]));               // full d for p-side
                cj = fminf(cj, fminf(e.x, e.y));
            }
            sred[c * 17 + ty] = cj;   // conflict-free: gcd(17,32)=1
        }
        __syncthreads();

        // commit prefetched tile (buffer nxt was last read in tile t-1)
        if (t + 1 < NTILE) {
            spx[nxt][tid] = pack2(pnx, pnx);
            spy[nxt][tid] = pack2(pny, pny);
            spz[nxt][tid] = pack2(pnz, pnz);
            spw[nxt][tid] = pack2(pnw, pnw);
        }

        // ---- dist2: every thread reduces one of the 256 columns ----
        {
            float mn = sred[tid * 17];
#pragma unroll
            for (int k = 1; k < 16; k++) mn = fminf(mn, sred[tid * 17 + k]);
            g_d2p[y][b * NM + mb0 + t * BM + tid] = mn;   // coalesced store
        }
        __syncthreads();
    }

    // ---- dist1 partial: once per block ----
#pragma unroll
    for (int k = 0; k < 8; k++)
        sred[(8 * ty + k) * 17 + tx] = rmin[k];
    __syncthreads();
    if (tid < 128) {
        float mn = sred[tid * 17];
#pragma unroll
        for (int k = 1; k < 16; k++) mn = fminf(mn, sred[tid * 17 + k]);
        g_d1p[s][b * NV + n0 + tid] = mn + scv[tid];      // coalesced store
    }
}

// ------------------------ 2) final reduction --------------------------------
// 256 blocks (64 per batch), 256 threads; parallel across the reduction dim.
// Mask via sentinel: invalid p-cols carry mins >= 1e10 (cp=BIGF), no pc reads.
__global__ void final_kernel(float* __restrict__ out) {
    __shared__ float4 p2[256];    // d2 stage-1 partials
    __shared__ float2 p1[256];    // d1 stage-1 partials
    __shared__ float sh[4];
    __shared__ bool last;
    int tid  = threadIdx.x;
    int b    = blockIdx.x >> 6;
    int part = blockIdx.x & 63;

    // ---- d2 stage 1: block covers 128 m-cols = 32 quads; 8 yy-groups of 4 ----
    {
        int q  = tid & 31;          // m-quad
        int yg = tid >> 5;          // yy-group (0..7)
        int m  = part * 128 + q * 4;
        float4 mn = make_float4(3.4e38f, 3.4e38f, 3.4e38f, 3.4e38f);
#pragma unroll
        for (int k = 0; k < 4; k++) {
            float4 v = *(const float4*)&g_d2p[yg * 4 + k][b * NM + m];
            mn.x = fminf(mn.x, v.x); mn.y = fminf(mn.y, v.y);
            mn.z = fminf(mn.z, v.z); mn.w = fminf(mn.w, v.w);
        }
        p2[tid] = mn;
    }
    // ---- d1 stage 1: block covers 64 v-rows = 32 pairs; 8 groups x 2 strips --
    {
        int pr = tid & 31;          // n-pair
        int sg = tid >> 5;          // strip-group (0..7) -> strips 2sg, 2sg+1
        int n  = part * 64 + pr * 2;
        float2 a = *(const float2*)&g_d1p[2 * sg][b * NV + n];
        float2 c = *(const float2*)&g_d1p[2 * sg + 1][b * NV + n];
        p1[tid] = make_float2(fminf(a.x, c.x), fminf(a.y, c.y));
    }
    __syncthreads();

    // ---- stage 2 + sentinel-masked accumulate ----
    float s1 = 0.f, s2 = 0.f, c2 = 0.f;
    if (tid < 32) {
        float4 mn = p2[tid];
#pragma unroll
        for (int k = 1; k < 8; k++) {
            float4 v = p2[tid + 32 * k];
            mn.x = fminf(mn.x, v.x); mn.y = fminf(mn.y, v.y);
            mn.z = fminf(mn.z, v.z); mn.w = fminf(mn.w, v.w);
        }
        if (mn.x < 1e9f) { s2 += mn.x; c2 += 1.f; }
        if (mn.y < 1e9f) { s2 += mn.y; c2 += 1.f; }
        if (mn.z < 1e9f) { s2 += mn.z; c2 += 1.f; }
        if (mn.w < 1e9f) { s2 += mn.w; c2 += 1.f; }
    } else if (tid < 64) {
        int pr = tid - 32;
        float2 mn = p1[pr];
#pragma unroll
        for (int k = 1; k < 8; k++) {
            float2 v = p1[pr + 32 * k];
            mn.x = fminf(mn.x, v.x); mn.y = fminf(mn.y, v.y);
        }
        s1 = mn.x + mn.y;
    }

#pragma unroll
    for (int o = 16; o > 0; o >>= 1) {
        s1 += __shfl_down_sync(0xffffffffu, s1, o);
        s2 += __shfl_down_sync(0xffffffffu, s2, o);
        c2 += __shfl_down_sync(0xffffffffu, c2, o);
    }
    if (tid == 0)  { sh[0] = s2; sh[1] = c2; }
    if (tid == 32) { sh[2] = s1; }
    __syncthreads();

    if (tid == 0) {
        atomicAdd(&g_sum1[b], sh[2]);
        atomicAdd(&g_sum2[b], sh[0]);
        atomicAdd(&g_cnt[b],  sh[1]);
        __threadfence();
        unsigned done = atomicAdd(&g_done, 1u);
        last = (done == gridDim.x - 1);
    }
    __syncthreads();

    if (last && tid == 0) {
        float acc = 0.f;
        for (int bb = 0; bb < BATCH; bb++)
            acc += g_sum1[bb] / (float)NV + g_sum2[bb] / fmaxf(g_cnt[bb], 1.f);
        out[0] = acc / (float)BATCH;
    }
}

// ------------------------ launch --------------------------------------------
extern "C" void kernel_launch(void* const* d_in, const int* in_sizes, int n_in,
                              void* d_out, int out_size) {
    const float* vert = (const float*)d_in[0];
    const float* pc   = (const float*)d_in[1];
    if (in_sizes[0] == BATCH * 3 * NM) {   // defensive input identification
        vert = (const float*)d_in[1];
        pc   = (const float*)d_in[0];
    }

    dim3 grid(NSTRIP, NVB, BATCH);
    chamfer_kernel<<<grid, 256>>>(vert, pc);
    final_kernel<<<256, 256>>>((float*)d_out);
}